// round 5
// baseline (speedup 1.0000x reference)
#include <cuda_runtime.h>

typedef unsigned long long u64;

#define Bn 256
#define Tn 256
#define Sn 20
#define NROWS (Bn*Tn)   // 65536

__device__ float g_zx[NROWS * 96];   // zx[row][96] = h_inner[row] @ Wo + bo

// ---------- packed f32x2 helpers ----------
__device__ __forceinline__ u64 ffma2(u64 a, u64 b, u64 c){
    u64 d;
    asm("fma.rn.f32x2 %0, %1, %2, %3;" : "=l"(d) : "l"(a), "l"(b), "l"(c));
    return d;
}
__device__ __forceinline__ u64 pk2(float lo, float hi){
    u64 r; asm("mov.b64 %0, {%1, %2};" : "=l"(r) : "f"(lo), "f"(hi)); return r;
}
__device__ __forceinline__ void up2(u64 v, float& lo, float& hi){
    asm("mov.b64 {%0, %1}, %2;" : "=f"(lo), "=f"(hi) : "l"(v));
}

// ---------- activations ----------
__device__ __forceinline__ float ex2f(float x){
    float r; asm("ex2.approx.ftz.f32 %0, %1;" : "=f"(r) : "f"(x)); return r;
}
__device__ __forceinline__ float rcpf(float x){
    float r; asm("rcp.approx.ftz.f32 %0, %1;" : "=f"(r) : "f"(x)); return r;
}
// exact-ish (err ~1e-7), used in outer (256 compounding steps)
__device__ __forceinline__ float sigf(float x){
    return rcpf(1.0f + ex2f(-1.4426950408889634f * x));
}
__device__ __forceinline__ float tanh_f(float x){
    return fmaf(-2.0f, rcpf(1.0f + ex2f(2.8853900817779268f * x)), 1.0f);
}
// HW tanh (1 MUFU op), used in inner (20 steps, shallow compounding)
__device__ __forceinline__ float tanha(float x){
    float r; asm("tanh.approx.f32 %0, %1;" : "=f"(r) : "f"(x)); return r;
}
__device__ __forceinline__ float sigt(float x){
    return fmaf(0.5f, tanha(0.5f * x), 0.5f);
}

// =====================================================================
// Inner LSTM: 65536 rows, S=20, U1=32, D=1.
// Block = 256 threads = 32 row-pair columns x 8 unit-groups (4 units each).
// h in SMEM as ulonglong2 [k/2][col] -> coalesced LDS.128 reads (16/step)
// and coalesced STS.128 writes. tanh.approx activations. 3 blocks/SM.
// =====================================================================
__global__ void __launch_bounds__(256, 3) inner_kernel(
    const float* __restrict__ x,  const float* __restrict__ Wi,
    const float* __restrict__ Ui, const float* __restrict__ bi,
    const float* __restrict__ Wo, const float* __restrict__ bo)
{
    extern __shared__ char smem[];
    float* wuf = (float*)smem;            // dup Ui [k][u][g][2]: 8192 f (32KB)
    float* wif = wuf + 8192;              // dup Wi [u][g][2]: 256 f
    float* bif = wif + 256;               // dup bi [u][g][2]: 256 f
    ulonglong2* hsm = (ulonglong2*)(bif + 256);  // [2][16 kpair][32 col] (16KB)

    const int tid = threadIdx.x;
    const int col = tid & 31;             // row-pair column (warp-lane)
    const int ug  = tid >> 5;             // unit group 0..7 (= warp id)
    const int ubase = ug * 4;

    // cooperative load + duplicate weights (gate order i,f,g,o: Ui col = g*32+u)
    for (int idx = tid; idx < 4096; idx += 256){
        int k = idx >> 7, cw = idx & 127;
        int g = cw >> 5,  u  = cw & 31;
        float w = Ui[idx];
        int o = (((k << 5) + u) * 4 + g) * 2;
        wuf[o] = w; wuf[o + 1] = w;
    }
    if (tid < 128){
        int g = tid >> 5, u = tid & 31;
        int o = (u * 4 + g) * 2;
        float w = Wi[tid]; wif[o] = w; wif[o + 1] = w;
        float b = bi[tid]; bif[o] = b; bif[o + 1] = b;
    }
    {   // h0 = 0 in both buffers' slot 0 region (buf 0 suffices, zero all)
        u64* hz = (u64*)hsm;
        for (int i = tid; i < 2048; i += 256) hz[i] = 0ULL;
    }
    __syncthreads();

    const ulonglong2* wu2 = (const ulonglong2*)wuf;
    const ulonglong2* wi2 = (const ulonglong2*)wif;
    const ulonglong2* bi2 = (const ulonglong2*)bif;

    float cA[4], cB[4];
    #pragma unroll
    for (int u8 = 0; u8 < 4; u8++){ cA[u8] = 0.f; cB[u8] = 0.f; }

    const long pair = (long)blockIdx.x * 32 + col;
    const float* x0p = x + (2 * pair) * Sn;
    const float* x1p = x + (2 * pair + 1) * Sn;
    float xn0 = __ldg(x0p), xn1 = __ldg(x1p);

    #pragma unroll 1
    for (int s = 0; s < Sn; s++){
        u64 xv = pk2(xn0, xn1);
        int sp = (s + 1 < Sn) ? s + 1 : s;
        xn0 = __ldg(x0p + sp); xn1 = __ldg(x1p + sp);   // branch-free prefetch
        const ulonglong2* hb = hsm + ((s & 1) << 9);         // read buffer
        ulonglong2*       hw = hsm + (((s + 1) & 1) << 9);   // write buffer

        u64 a[4][4];
        #pragma unroll
        for (int u8 = 0; u8 < 4; u8++){
            int u = ubase + u8;
            ulonglong2 wA = wi2[u * 2], wB = wi2[u * 2 + 1];
            ulonglong2 bA = bi2[u * 2], bB = bi2[u * 2 + 1];
            a[u8][0] = ffma2(xv, wA.x, bA.x);
            a[u8][1] = ffma2(xv, wA.y, bA.y);
            a[u8][2] = ffma2(xv, wB.x, bB.x);
            a[u8][3] = ffma2(xv, wB.y, bB.y);
        }
        #pragma unroll 8
        for (int j = 0; j < 16; j++){
            ulonglong2 hp = hb[(j << 5) + col];       // h[2j], h[2j+1] (coalesced)
            int k0 = 2 * j;
            #pragma unroll
            for (int u8 = 0; u8 < 4; u8++){
                int wo0 = ((k0 << 5) + ubase + u8) << 1;
                ulonglong2 w01 = wu2[wo0], w23 = wu2[wo0 + 1];
                a[u8][0] = ffma2(hp.x, w01.x, a[u8][0]);
                a[u8][1] = ffma2(hp.x, w01.y, a[u8][1]);
                a[u8][2] = ffma2(hp.x, w23.x, a[u8][2]);
                a[u8][3] = ffma2(hp.x, w23.y, a[u8][3]);
                int wo1 = (((k0 + 1) << 5) + ubase + u8) << 1;
                ulonglong2 v01 = wu2[wo1], v23 = wu2[wo1 + 1];
                a[u8][0] = ffma2(hp.y, v01.x, a[u8][0]);
                a[u8][1] = ffma2(hp.y, v01.y, a[u8][1]);
                a[u8][2] = ffma2(hp.y, v23.x, a[u8][2]);
                a[u8][3] = ffma2(hp.y, v23.y, a[u8][3]);
            }
        }
        u64 hv[4];
        #pragma unroll
        for (int u8 = 0; u8 < 4; u8++){
            float zi0, zi1, zf0, zf1, zg0, zg1, zo0, zo1;
            up2(a[u8][0], zi0, zi1);
            up2(a[u8][1], zf0, zf1);
            up2(a[u8][2], zg0, zg1);
            up2(a[u8][3], zo0, zo1);
            float i0 = sigt(zi0),  i1 = sigt(zi1);
            float f0 = sigt(zf0),  f1 = sigt(zf1);
            float g0 = tanha(zg0), g1 = tanha(zg1);
            float o0 = sigt(zo0),  o1 = sigt(zo1);
            float c0 = f0 * cA[u8] + i0 * g0;
            float c1 = f1 * cB[u8] + i1 * g1;
            cA[u8] = c0; cB[u8] = c1;
            hv[u8] = pk2(o0 * tanha(c0), o1 * tanha(c1));
        }
        {   // coalesced 16B stores: unit pairs (ubase,ubase+1), (ubase+2,ubase+3)
            int j0 = ubase >> 1;
            ulonglong2 p0; p0.x = hv[0]; p0.y = hv[1];
            ulonglong2 p1; p1.x = hv[2]; p1.y = hv[3];
            hw[(j0 << 5) + col]       = p0;
            hw[((j0 + 1) << 5) + col] = p1;
        }
        __syncthreads();
    }

    // epilogue: zx = h_final @ Wo + bo (final h in buffer 0, Sn even).
    // unit-group ug computes 12 of the 96 output columns.
    const ulonglong2* hf = hsm;
    const long r0 = 2 * pair, r1 = r0 + 1;
    float* z0p = g_zx + r0 * 96 + ug * 12;
    float* z1p = g_zx + r1 * 96 + ug * 12;
    #pragma unroll 1
    for (int c4 = 0; c4 < 3; c4++){
        float4 b4 = __ldg((const float4*)(bo + ug * 12 + c4 * 4));
        u64 ac0 = pk2(b4.x, b4.x), ac1 = pk2(b4.y, b4.y);
        u64 ac2 = pk2(b4.z, b4.z), ac3 = pk2(b4.w, b4.w);
        #pragma unroll 4
        for (int j = 0; j < 16; j++){
            ulonglong2 hp = hf[(j << 5) + col];
            float4 wa = __ldg((const float4*)(Wo + (2 * j) * 96     + ug * 12 + c4 * 4));
            float4 wb = __ldg((const float4*)(Wo + (2 * j + 1) * 96 + ug * 12 + c4 * 4));
            ac0 = ffma2(hp.x, pk2(wa.x, wa.x), ac0);
            ac1 = ffma2(hp.x, pk2(wa.y, wa.y), ac1);
            ac2 = ffma2(hp.x, pk2(wa.z, wa.z), ac2);
            ac3 = ffma2(hp.x, pk2(wa.w, wa.w), ac3);
            ac0 = ffma2(hp.y, pk2(wb.x, wb.x), ac0);
            ac1 = ffma2(hp.y, pk2(wb.y, wb.y), ac1);
            ac2 = ffma2(hp.y, pk2(wb.z, wb.z), ac2);
            ac3 = ffma2(hp.y, pk2(wb.w, wb.w), ac3);
        }
        float a0l,a0h,a1l,a1h,a2l,a2h,a3l,a3h;
        up2(ac0,a0l,a0h); up2(ac1,a1l,a1h); up2(ac2,a2l,a2h); up2(ac3,a3l,a3h);
        *(float4*)(z0p + c4 * 4) = make_float4(a0l, a1l, a2l, a3l);
        *(float4*)(z1p + c4 * 4) = make_float4(a0h, a1h, a2h, a3h);
    }
}

// =====================================================================
// Outer LSTM + dense head: one warp per batch row. Register weights
// (scalar, per gate). 8 independent FMA chains (depth 12). Prefetch ring
// depth 4 (branch-free clamped) hides L2 latency of g_zx loads.
// =====================================================================
__global__ void __launch_bounds__(32) outer_kernel(
    const int*   __restrict__ lengths,
    const float* __restrict__ Uo,
    const float* __restrict__ Wd,
    const float* __restrict__ bd,
    float*       __restrict__ out)
{
    const int l  = threadIdx.x;
    const int la = (l < 24) ? l : 0;       // clamped lane
    const int b  = blockIdx.x;

    float wI[24], wF[24], wG[24], wO[24];
    #pragma unroll
    for (int k = 0; k < 24; k++){
        const float* row = Uo + k * 96;
        wI[k] = __ldg(row + la);
        wF[k] = __ldg(row + 24 + la);
        wG[k] = __ldg(row + 48 + la);
        wO[k] = __ldg(row + 72 + la);
    }

    const int len = lengths[b];            // in [1, T]
    const float* zr = g_zx + (size_t)b * Tn * 96;

    // prefetch ring, depth 4 (clamped)
    float r0[4], r1[4], r2[4], r3[4];
    #pragma unroll
    for (int d = 0; d < 4; d++){
        int td = (d < len) ? d : len - 1;
        const float* zq = zr + (size_t)td * 96;
        r0[d] = zq[la]; r1[d] = zq[24 + la];
        r2[d] = zq[48 + la]; r3[d] = zq[72 + la];
    }

    float h = 0.f, c = 0.f;

    for (int t = 0; t < len; t++){
        int slot = t & 3;
        float z0 = r0[slot], z1 = r1[slot], z2 = r2[slot], z3 = r3[slot];
        {   // branch-free prefetch of step t+4 (clamped)
            int tp = (t + 4 < len) ? t + 4 : len - 1;
            const float* zq = zr + (size_t)tp * 96;
            r0[slot] = zq[la]; r1[slot] = zq[24 + la];
            r2[slot] = zq[48 + la]; r3[slot] = zq[72 + la];
        }
        // 8 independent chains of depth 12
        float zi0 = z0, zi1 = 0.f, zf0 = z1, zf1 = 0.f;
        float zg0 = z2, zg1 = 0.f, zo0 = z3, zo1 = 0.f;
        #pragma unroll
        for (int j = 0; j < 12; j++){
            float ha = __shfl_sync(0xffffffffu, h, j);
            float hb2 = __shfl_sync(0xffffffffu, h, j + 12);
            zi0 = fmaf(ha, wI[j], zi0);   zi1 = fmaf(hb2, wI[j + 12], zi1);
            zf0 = fmaf(ha, wF[j], zf0);   zf1 = fmaf(hb2, wF[j + 12], zf1);
            zg0 = fmaf(ha, wG[j], zg0);   zg1 = fmaf(hb2, wG[j + 12], zg1);
            zo0 = fmaf(ha, wO[j], zo0);   zo1 = fmaf(hb2, wO[j + 12], zo1);
        }
        float fi = sigf(zi0 + zi1), ff = sigf(zf0 + zf1);
        float gg = tanh_f(zg0 + zg1), oo = sigf(zo0 + zo1);
        c = fmaf(ff, c, fi * gg);
        h = oo * tanh_f(c);
        // lanes >= 24 compute finite garbage, never read (shfl uses k < 24)
    }

    // dense sigmoid head
    float p = (l < 24) ? h * __ldg(Wd + la) : 0.f;
    #pragma unroll
    for (int off = 16; off; off >>= 1) p += __shfl_xor_sync(0xffffffffu, p, off);
    if (l == 0) out[b] = sigf(p + bd[0]);
}

extern "C" void kernel_launch(void* const* d_in, const int* in_sizes, int n_in,
                              void* d_out, int out_size)
{
    const float* x       = (const float*)d_in[0];
    const int*   lengths = (const int*)  d_in[1];
    const float* Wi      = (const float*)d_in[2];
    const float* Ui      = (const float*)d_in[3];
    const float* bi      = (const float*)d_in[4];
    const float* Wo      = (const float*)d_in[5];
    const float* Uo      = (const float*)d_in[6];
    const float* bo      = (const float*)d_in[7];
    const float* Wd      = (const float*)d_in[8];
    const float* bd      = (const float*)d_in[9];
    float* out = (float*)d_out;

    // smem: wuf 32768 + wif 1024 + bif 1024 + hsm 16384 = 51200
    const int smem_bytes = 51200;
    cudaFuncSetAttribute(inner_kernel,
                         cudaFuncAttributeMaxDynamicSharedMemorySize, smem_bytes);

    inner_kernel<<<1024, 256, smem_bytes>>>(x, Wi, Ui, bi, Wo, bo);
    outer_kernel<<<256, 32>>>(lengths, Uo, Wd, bd, out);
}

// round 6
// speedup vs baseline: 1.2272x; 1.2272x over previous
#include <cuda_runtime.h>

typedef unsigned long long u64;

#define Bn 256
#define Tn 256
#define Sn 20
#define NROWS (Bn*Tn)   // 65536

__device__ float g_zx[NROWS * 96];   // zx[row][96] = h_inner[row] @ Wo + bo

// ---------- packed f32x2 helpers ----------
__device__ __forceinline__ u64 ffma2(u64 a, u64 b, u64 c){
    u64 d;
    asm("fma.rn.f32x2 %0, %1, %2, %3;" : "=l"(d) : "l"(a), "l"(b), "l"(c));
    return d;
}
__device__ __forceinline__ u64 add2(u64 a, u64 b){
    u64 d;
    asm("add.rn.f32x2 %0, %1, %2;" : "=l"(d) : "l"(a), "l"(b));
    return d;
}
__device__ __forceinline__ u64 pk2(float lo, float hi){
    u64 r; asm("mov.b64 %0, {%1, %2};" : "=l"(r) : "f"(lo), "f"(hi)); return r;
}
__device__ __forceinline__ void up2(u64 v, float& lo, float& hi){
    asm("mov.b64 {%0, %1}, %2;" : "=f"(lo), "=f"(hi) : "l"(v));
}

// ---------- activations: HW tanh (validated: rel_err unchanged) ----------
__device__ __forceinline__ float tanha(float x){
    float r; asm("tanh.approx.f32 %0, %1;" : "=f"(r) : "f"(x)); return r;
}
__device__ __forceinline__ float sigt(float x){
    return fmaf(0.5f, tanha(0.5f * x), 0.5f);
}

// =====================================================================
// Inner LSTM: 65536 rows, S=20, U1=32, D=1.
// Block = 256 thr = 8 unit-groups x 32 col-groups; each thread owns TWO
// row-pairs (4 rows) x 4 units -> weight LDS amortized 2x (crossbar was
// co-bottleneck with FMA pipe). h in SMEM ulonglong2 [buf][j][64 rp],
// coalesced LDS/STS.128. One __syncthreads per step.
// =====================================================================
__global__ void __launch_bounds__(256, 2) inner_kernel(
    const float* __restrict__ x,  const float* __restrict__ Wi,
    const float* __restrict__ Ui, const float* __restrict__ bi,
    const float* __restrict__ Wo, const float* __restrict__ bo)
{
    extern __shared__ char smem[];
    float* wuf = (float*)smem;            // dup Ui [k][u][g][2]: 8192 f (32KB)
    float* wif = wuf + 8192;              // dup Wi [u][g][2]: 256 f
    float* bif = wif + 256;               // dup bi [u][g][2]: 256 f
    ulonglong2* hsm = (ulonglong2*)(bif + 256);  // [2][16 j][64 rp] (32KB)

    const int tid = threadIdx.x;
    const int cg  = tid & 31;             // col-group: row-pairs cg and cg+32
    const int ug  = tid >> 5;             // unit group 0..7
    const int ubase = ug * 4;

    // cooperative load + duplicate weights (gate order i,f,g,o: Ui col = g*32+u)
    for (int idx = tid; idx < 4096; idx += 256){
        int k = idx >> 7, cw = idx & 127;
        int g = cw >> 5,  u  = cw & 31;
        float w = Ui[idx];
        int o = (((k << 5) + u) * 4 + g) * 2;
        wuf[o] = w; wuf[o + 1] = w;
    }
    if (tid < 128){
        int g = tid >> 5, u = tid & 31;
        int o = (u * 4 + g) * 2;
        float w = Wi[tid]; wif[o] = w; wif[o + 1] = w;
        float b = bi[tid]; bif[o] = b; bif[o + 1] = b;
    }
    {   // h0 = 0 (buffer 0)
        u64* hz = (u64*)hsm;
        for (int i = tid; i < 4096; i += 256) hz[i] = 0ULL;
    }
    __syncthreads();

    const ulonglong2* wu2 = (const ulonglong2*)wuf;
    const ulonglong2* wi2 = (const ulonglong2*)wif;
    const ulonglong2* bi2 = (const ulonglong2*)bif;

    // c state: packs P (rows 2cg,2cg+1) and Q (rows 64+2cg, 64+2cg+1)
    float cA[4], cB[4], cC[4], cD[4];
    #pragma unroll
    for (int u8 = 0; u8 < 4; u8++){ cA[u8]=0.f; cB[u8]=0.f; cC[u8]=0.f; cD[u8]=0.f; }

    const long rowbase = (long)blockIdx.x * 128;
    const float* x0p = x + (rowbase + 2 * cg) * Sn;
    const float* x1p = x0p + Sn;
    const float* x2p = x + (rowbase + 64 + 2 * cg) * Sn;
    const float* x3p = x2p + Sn;
    float xn0 = __ldg(x0p), xn1 = __ldg(x1p);
    float xn2 = __ldg(x2p), xn3 = __ldg(x3p);

    #pragma unroll 1
    for (int s = 0; s < Sn; s++){
        u64 xvP = pk2(xn0, xn1);
        u64 xvQ = pk2(xn2, xn3);
        int sp = (s + 1 < Sn) ? s + 1 : s;
        xn0 = __ldg(x0p + sp); xn1 = __ldg(x1p + sp);
        xn2 = __ldg(x2p + sp); xn3 = __ldg(x3p + sp);
        const ulonglong2* hb = hsm + ((s & 1) << 10);         // [16 j][64 rp]
        ulonglong2*       hw = hsm + (((s + 1) & 1) << 10);

        u64 aP[4][4], aQ[4][4];
        #pragma unroll
        for (int u8 = 0; u8 < 4; u8++){
            int u = ubase + u8;
            ulonglong2 wA = wi2[u * 2], wB = wi2[u * 2 + 1];
            ulonglong2 bA = bi2[u * 2], bB = bi2[u * 2 + 1];
            aP[u8][0] = ffma2(xvP, wA.x, bA.x);
            aP[u8][1] = ffma2(xvP, wA.y, bA.y);
            aP[u8][2] = ffma2(xvP, wB.x, bB.x);
            aP[u8][3] = ffma2(xvP, wB.y, bB.y);
            aQ[u8][0] = ffma2(xvQ, wA.x, bA.x);
            aQ[u8][1] = ffma2(xvQ, wA.y, bA.y);
            aQ[u8][2] = ffma2(xvQ, wB.x, bB.x);
            aQ[u8][3] = ffma2(xvQ, wB.y, bB.y);
        }
        #pragma unroll 4
        for (int j = 0; j < 16; j++){
            ulonglong2 hP = hb[(j << 6) + cg];        // h[2j],h[2j+1], pack P
            ulonglong2 hQ = hb[(j << 6) + cg + 32];   // pack Q
            int k0 = 2 * j;
            #pragma unroll
            for (int u8 = 0; u8 < 4; u8++){
                int wo0 = ((k0 << 5) + ubase + u8) << 1;
                ulonglong2 w01 = wu2[wo0], w23 = wu2[wo0 + 1];
                int wo1 = (((k0 + 1) << 5) + ubase + u8) << 1;
                ulonglong2 v01 = wu2[wo1], v23 = wu2[wo1 + 1];
                aP[u8][0] = ffma2(hP.x, w01.x, aP[u8][0]);
                aP[u8][1] = ffma2(hP.x, w01.y, aP[u8][1]);
                aP[u8][2] = ffma2(hP.x, w23.x, aP[u8][2]);
                aP[u8][3] = ffma2(hP.x, w23.y, aP[u8][3]);
                aP[u8][0] = ffma2(hP.y, v01.x, aP[u8][0]);
                aP[u8][1] = ffma2(hP.y, v01.y, aP[u8][1]);
                aP[u8][2] = ffma2(hP.y, v23.x, aP[u8][2]);
                aP[u8][3] = ffma2(hP.y, v23.y, aP[u8][3]);
                aQ[u8][0] = ffma2(hQ.x, w01.x, aQ[u8][0]);
                aQ[u8][1] = ffma2(hQ.x, w01.y, aQ[u8][1]);
                aQ[u8][2] = ffma2(hQ.x, w23.x, aQ[u8][2]);
                aQ[u8][3] = ffma2(hQ.x, w23.y, aQ[u8][3]);
                aQ[u8][0] = ffma2(hQ.y, v01.x, aQ[u8][0]);
                aQ[u8][1] = ffma2(hQ.y, v01.y, aQ[u8][1]);
                aQ[u8][2] = ffma2(hQ.y, v23.x, aQ[u8][2]);
                aQ[u8][3] = ffma2(hQ.y, v23.y, aQ[u8][3]);
            }
        }
        u64 hvP[4], hvQ[4];
        #pragma unroll
        for (int u8 = 0; u8 < 4; u8++){
            float zi0,zi1,zf0,zf1,zg0,zg1,zo0,zo1;
            up2(aP[u8][0], zi0, zi1);
            up2(aP[u8][1], zf0, zf1);
            up2(aP[u8][2], zg0, zg1);
            up2(aP[u8][3], zo0, zo1);
            float c0 = sigt(zf0) * cA[u8] + sigt(zi0) * tanha(zg0);
            float c1 = sigt(zf1) * cB[u8] + sigt(zi1) * tanha(zg1);
            cA[u8] = c0; cB[u8] = c1;
            hvP[u8] = pk2(sigt(zo0) * tanha(c0), sigt(zo1) * tanha(c1));

            up2(aQ[u8][0], zi0, zi1);
            up2(aQ[u8][1], zf0, zf1);
            up2(aQ[u8][2], zg0, zg1);
            up2(aQ[u8][3], zo0, zo1);
            float c2 = sigt(zf0) * cC[u8] + sigt(zi0) * tanha(zg0);
            float c3 = sigt(zf1) * cD[u8] + sigt(zi1) * tanha(zg1);
            cC[u8] = c2; cD[u8] = c3;
            hvQ[u8] = pk2(sigt(zo0) * tanha(c2), sigt(zo1) * tanha(c3));
        }
        {   // coalesced 16B stores (unit pairs)
            int j0 = ubase >> 1;
            ulonglong2 p0; p0.x = hvP[0]; p0.y = hvP[1];
            ulonglong2 p1; p1.x = hvP[2]; p1.y = hvP[3];
            ulonglong2 q0; q0.x = hvQ[0]; q0.y = hvQ[1];
            ulonglong2 q1; q1.x = hvQ[2]; q1.y = hvQ[3];
            hw[(j0 << 6) + cg]            = p0;
            hw[((j0 + 1) << 6) + cg]      = p1;
            hw[(j0 << 6) + cg + 32]       = q0;
            hw[((j0 + 1) << 6) + cg + 32] = q1;
        }
        __syncthreads();
    }

    // epilogue: zx = h_final @ Wo + bo (final h in buffer 0, Sn even).
    // unit-group ug computes 12 of 96 cols, for both its row-pairs.
    const ulonglong2* hf = hsm;
    #pragma unroll 1
    for (int half = 0; half < 2; half++){
        int rp = cg + half * 32;
        long r0 = rowbase + 2 * (half * 32 + cg);
        float* z0p = g_zx + r0 * 96 + ug * 12;
        float* z1p = z0p + 96;
        #pragma unroll 1
        for (int c4 = 0; c4 < 3; c4++){
            float4 b4 = __ldg((const float4*)(bo + ug * 12 + c4 * 4));
            u64 ac0 = pk2(b4.x, b4.x), ac1 = pk2(b4.y, b4.y);
            u64 ac2 = pk2(b4.z, b4.z), ac3 = pk2(b4.w, b4.w);
            #pragma unroll 4
            for (int j = 0; j < 16; j++){
                ulonglong2 hp = hf[(j << 6) + rp];
                float4 wa = __ldg((const float4*)(Wo + (2*j)*96     + ug*12 + c4*4));
                float4 wb = __ldg((const float4*)(Wo + (2*j + 1)*96 + ug*12 + c4*4));
                ac0 = ffma2(hp.x, pk2(wa.x, wa.x), ac0);
                ac1 = ffma2(hp.x, pk2(wa.y, wa.y), ac1);
                ac2 = ffma2(hp.x, pk2(wa.z, wa.z), ac2);
                ac3 = ffma2(hp.x, pk2(wa.w, wa.w), ac3);
                ac0 = ffma2(hp.y, pk2(wb.x, wb.x), ac0);
                ac1 = ffma2(hp.y, pk2(wb.y, wb.y), ac1);
                ac2 = ffma2(hp.y, pk2(wb.z, wb.z), ac2);
                ac3 = ffma2(hp.y, pk2(wb.w, wb.w), ac3);
            }
            float a0l,a0h,a1l,a1h,a2l,a2h,a3l,a3h;
            up2(ac0,a0l,a0h); up2(ac1,a1l,a1h); up2(ac2,a2l,a2h); up2(ac3,a3l,a3h);
            *(float4*)(z0p + c4 * 4) = make_float4(a0l, a1l, a2l, a3l);
            *(float4*)(z1p + c4 * 4) = make_float4(a0h, a1h, a2h, a3h);
        }
    }
}

// =====================================================================
// Outer LSTM + dense head: one warp per batch row. Packed register
// weights; static depth-2 prefetch via manual 2x unroll (NO dynamic
// array indexing -> no local memory). Split chains depth 12+12.
// =====================================================================
__device__ __forceinline__ void outer_step(
    float& h, float& c, u64 zA, u64 zB,
    const u64* w_if, const u64* w_go)
{
    u64 a0 = zA, a1 = 0ULL, b0 = zB, b1 = 0ULL;
    #pragma unroll
    for (int j = 0; j < 12; j++){
        float h0 = __shfl_sync(0xffffffffu, h, j);
        float h1 = __shfl_sync(0xffffffffu, h, j + 12);
        u64 H0 = pk2(h0, h0), H1 = pk2(h1, h1);
        a0 = ffma2(H0, w_if[j],      a0);
        b0 = ffma2(H0, w_go[j],      b0);
        a1 = ffma2(H1, w_if[j + 12], a1);
        b1 = ffma2(H1, w_go[j + 12], b1);
    }
    u64 zAf = add2(a0, a1);
    u64 zBf = add2(b0, b1);
    float zi, zf, zg, zo;
    up2(zAf, zi, zf);
    up2(zBf, zg, zo);
    float fi = sigt(zi), ff = sigt(zf), gg = tanha(zg), oo = sigt(zo);
    c = fmaf(ff, c, fi * gg);
    h = oo * tanha(c);
}

__global__ void __launch_bounds__(32) outer_kernel(
    const int*   __restrict__ lengths,
    const float* __restrict__ Uo,
    const float* __restrict__ Wd,
    const float* __restrict__ bd,
    float*       __restrict__ out)
{
    const int l  = threadIdx.x;
    const int la = (l < 24) ? l : 0;       // clamped lane
    const int b  = blockIdx.x;

    u64 w_if[24], w_go[24];
    #pragma unroll
    for (int k = 0; k < 24; k++){
        const float* row = Uo + k * 96;
        w_if[k] = pk2(__ldg(row + la),      __ldg(row + 24 + la));
        w_go[k] = pk2(__ldg(row + 48 + la), __ldg(row + 72 + la));
    }

    const int len = lengths[b];            // in [1, T]
    const float* zr = g_zx + (size_t)b * Tn * 96;

    // static two-slot prefetch
    u64 A0, B0, A1, B1;
    A0 = pk2(zr[la], zr[24 + la]);
    B0 = pk2(zr[48 + la], zr[72 + la]);
    {
        const float* z1 = zr + ((len > 1) ? 96 : 0);
        A1 = pk2(z1[la], z1[24 + la]);
        B1 = pk2(z1[48 + la], z1[72 + la]);
    }

    float h = 0.f, c = 0.f;
    int t = 0;
    while (t < len){
        {   // even step: consume slot0, prefetch t+2 into slot0
            u64 zA = A0, zB = B0;
            int tp = (t + 2 < len) ? t + 2 : len - 1;
            const float* zq = zr + (size_t)tp * 96;
            A0 = pk2(zq[la], zq[24 + la]);
            B0 = pk2(zq[48 + la], zq[72 + la]);
            outer_step(h, c, zA, zB, w_if, w_go);
        }
        t++;
        if (t >= len) break;
        {   // odd step: consume slot1, prefetch t+2 into slot1
            u64 zA = A1, zB = B1;
            int tp = (t + 2 < len) ? t + 2 : len - 1;
            const float* zq = zr + (size_t)tp * 96;
            A1 = pk2(zq[la], zq[24 + la]);
            B1 = pk2(zq[48 + la], zq[72 + la]);
            outer_step(h, c, zA, zB, w_if, w_go);
        }
        t++;
    }

    // dense sigmoid head: out[b] = sigmoid(h . Wd + bd)
    float p = (l < 24) ? h * __ldg(Wd + la) : 0.f;
    #pragma unroll
    for (int off = 16; off; off >>= 1) p += __shfl_xor_sync(0xffffffffu, p, off);
    if (l == 0) out[b] = fmaf(0.5f, tanha(0.5f * (p + bd[0])), 0.5f);
}

extern "C" void kernel_launch(void* const* d_in, const int* in_sizes, int n_in,
                              void* d_out, int out_size)
{
    const float* x       = (const float*)d_in[0];
    const int*   lengths = (const int*)  d_in[1];
    const float* Wi      = (const float*)d_in[2];
    const float* Ui      = (const float*)d_in[3];
    const float* bi      = (const float*)d_in[4];
    const float* Wo      = (const float*)d_in[5];
    const float* Uo      = (const float*)d_in[6];
    const float* bo      = (const float*)d_in[7];
    const float* Wd      = (const float*)d_in[8];
    const float* bd      = (const float*)d_in[9];
    float* out = (float*)d_out;

    // smem: wuf 32768 + wif 1024 + bif 1024 + hsm 32768 = 67584
    const int smem_bytes = 67584;
    cudaFuncSetAttribute(inner_kernel,
                         cudaFuncAttributeMaxDynamicSharedMemorySize, smem_bytes);

    inner_kernel<<<512, 256, smem_bytes>>>(x, Wi, Ui, bi, Wo, bo);
    outer_kernel<<<256, 32>>>(lengths, Uo, Wd, bd, out);
}

// round 8
// speedup vs baseline: 2.1975x; 1.7907x over previous
#include <cuda_runtime.h>
#include <cuda_bf16.h>
#include <cstdint>

typedef unsigned long long u64;

#define Bn 256
#define Tn 256
#define Sn 20
#define NROWS (Bn*Tn)   // 65536

__device__ float g_zx[NROWS * 96];   // zx[row][96] = h_inner[row] @ Wo + bo

// ---------- packed f32x2 helpers (outer kernel) ----------
__device__ __forceinline__ u64 ffma2(u64 a, u64 b, u64 c){
    u64 d;
    asm("fma.rn.f32x2 %0, %1, %2, %3;" : "=l"(d) : "l"(a), "l"(b), "l"(c));
    return d;
}
__device__ __forceinline__ u64 add2(u64 a, u64 b){
    u64 d;
    asm("add.rn.f32x2 %0, %1, %2;" : "=l"(d) : "l"(a), "l"(b));
    return d;
}
__device__ __forceinline__ u64 pk2(float lo, float hi){
    u64 r; asm("mov.b64 %0, {%1, %2};" : "=l"(r) : "f"(lo), "f"(hi)); return r;
}
__device__ __forceinline__ void up2(u64 v, float& lo, float& hi){
    asm("mov.b64 {%0, %1}, %2;" : "=f"(lo), "=f"(hi) : "l"(v));
}

// ---------- activations ----------
__device__ __forceinline__ float tanha(float x){
    float r; asm("tanh.approx.f32 %0, %1;" : "=f"(r) : "f"(x)); return r;
}
__device__ __forceinline__ float sigt(float x){
    return fmaf(0.5f, tanha(0.5f * x), 0.5f);
}

// ---------- smem / swizzle ----------
__device__ __forceinline__ uint32_t smem_to_u32(const void* p){
    uint32_t a;
    asm("{ .reg .u64 t; cvta.to.shared.u64 t, %1; cvt.u32.u64 %0, t; }"
        : "=r"(a) : "l"(p));
    return a;
}
#define SWZ(bo) ((bo) ^ (((bo) >> 3) & 0x70))

// ---------- mma.sync / ldmatrix (baseline PTX, compiles for sm_103) ----------
#define MMA_BF16(d, a, b0v, b1v) \
    asm volatile("mma.sync.aligned.m16n8k16.row.col.f32.bf16.bf16.f32 " \
        "{%0,%1,%2,%3}, {%4,%5,%6,%7}, {%8,%9}, {%0,%1,%2,%3};" \
        : "+f"((d)[0]), "+f"((d)[1]), "+f"((d)[2]), "+f"((d)[3]) \
        : "r"((a)[0]), "r"((a)[1]), "r"((a)[2]), "r"((a)[3]), "r"(b0v), "r"(b1v))

#define LDSM4(r, addr) \
    asm volatile("ldmatrix.sync.aligned.m8n8.x4.shared.b16 {%0,%1,%2,%3}, [%4];" \
        : "=r"((r)[0]), "=r"((r)[1]), "=r"((r)[2]), "=r"((r)[3]) : "r"(addr))

// SMEM layout (bytes); A/B tiles: [128][64] bf16 = 128B rows, SW128-swizzled
#define OFF_AH 0
#define OFF_AL 16384
#define OFF_BH 32768
#define OFF_BL 49152
#define OFF_WO 65536    // 32*96 f32 = 12288
#define OFF_BO 77824    // 96 f32
#define SMEM_SZ 78208

// =====================================================================
// Inner LSTM via warp-level bf16 mma.sync. 512 blocks x 256 thr (8 warps).
// Warp w owns rows 16w..16w+15 -- fully independent (no block sync in loop).
// Per step: D[16x128] = A[16x48] x B[48x128], 3-product bf16 hi/lo split.
// B cols: [i,f interleaved x32u | g,o interleaved x32u] so every lane holds
// all 4 gates of its units in D frags. h written back bf16 hi/lo into A.
// =====================================================================
__global__ void __launch_bounds__(256) inner_mma(
    const float* __restrict__ x,  const float* __restrict__ Wi,
    const float* __restrict__ Ui, const float* __restrict__ bi,
    const float* __restrict__ Wo, const float* __restrict__ bo)
{
    extern __shared__ char smc[];
    const uint32_t sb = smem_to_u32(smc);
    const int tid  = threadIdx.x;
    const int wid  = tid >> 5;
    const int lane = tid & 31;
    const int q    = lane & 3;
    const int rr   = lane >> 2;            // 0..7
    const int wrow0 = wid * 16;            // warp's first local row

    // --- build B tiles (hi/lo): n-row = permuted gate col, k = [Ui | Wi | bi | 0] ---
    for (int idx = tid; idx < 128 * 64; idx += 256){
        int n = idx >> 6, k = idx & 63;
        int u, g;
        if (n < 64){ u = n >> 1; g = n & 1; }          // i,f block
        else       { u = (n - 64) >> 1; g = 2 + (n & 1); }  // g,o block
        int col = g * 32 + u;
        float w = 0.f;
        if (k < 32)       w = Ui[k * 128 + col];
        else if (k == 32) w = Wi[col];
        else if (k == 33) w = bi[col];
        __nv_bfloat16 wh = __float2bfloat16(w);
        float wl = w - __bfloat162float(wh);
        uint32_t off = SWZ((uint32_t)(n * 128 + k * 2));
        *(__nv_bfloat16*)(smc + OFF_BH + off) = wh;
        *(__nv_bfloat16*)(smc + OFF_BL + off) = __float2bfloat16(wl);
    }
    // --- zero A tiles (h0=0, pads=0) ---
    for (int i = tid; i < 4096; i += 256){
        ((uint32_t*)(smc + OFF_AH))[i] = 0u;
        ((uint32_t*)(smc + OFF_AL))[i] = 0u;
    }
    // --- stage Wo/bo for zx epilogue ---
    {
        float* wos = (float*)(smc + OFF_WO);
        for (int i = tid; i < 32 * 96; i += 256) wos[i] = Wo[i];
        float* bos = (float*)(smc + OFF_BO);
        if (tid < 96) bos[tid] = bo[tid];
    }
    __syncthreads();

    // --- loop-invariant ldmatrix addresses (SWZ additive in +32*kc here) ---
    // A: m0=rows0-7 b0, m1=rows8-15 b0, m2=rows0-7 b16, m3=rows8-15 b16
    const uint32_t aRow  = wrow0 + (lane & 15);
    const uint32_t aByte = (uint32_t)(lane >> 4) << 4;
    const uint32_t aoffH = sb + OFF_AH + SWZ(aRow * 128 + aByte);
    const uint32_t aoffL = aoffH + 16384;
    // B: m0=(n0-7,b0), m1=(n0-7,b16), m2=(n8-15,b0), m3=(n8-15,b16)
    uint32_t boffH[8];
    {
        uint32_t nrow = ((uint32_t)(lane >> 4) << 3) + (lane & 7);
        uint32_t bbyte = ((uint32_t)((lane >> 3) & 1)) << 4;
        #pragma unroll
        for (int np = 0; np < 8; np++)
            boffH[np] = sb + OFF_BH + SWZ((16 * np + nrow) * 128 + bbyte);
    }
    // x column write offset (lane < 16 handles one row)
    const uint32_t xoff = SWZ((uint32_t)((wrow0 + (lane & 15)) * 128 + 64));

    // x prefetch
    const long grow = (long)blockIdx.x * 128 + wrow0 + (lane & 15);
    const float* xrow = x + grow * Sn;
    float xnext = __ldg(xrow);

    float cst[16];
    #pragma unroll
    for (int i = 0; i < 16; i++) cst[i] = 0.f;

    const int row0 = wrow0 + rr;       // local rows this lane owns
    const int row1 = row0 + 8;

    #pragma unroll 1
    for (int s = 0; s < Sn; s++){
        // write x & one columns for this step (h written last step)
        if (lane < 16){
            float xv = xnext;
            int sp = (s + 1 < Sn) ? s + 1 : s;
            xnext = __ldg(xrow + sp);
            __nv_bfloat16 xh = __float2bfloat16(xv);
            float xl = xv - __bfloat162float(xh);
            uint32_t hi = (0x3F80u << 16) | (uint32_t)__bfloat16_as_ushort(xh);
            uint32_t lo = (uint32_t)__bfloat16_as_ushort(__float2bfloat16(xl));
            *(uint32_t*)(smc + OFF_AH + xoff) = hi;
            *(uint32_t*)(smc + OFF_AL + xoff) = lo;
        }
        __syncwarp();

        uint32_t ah[3][4], al[3][4];
        #pragma unroll
        for (int kc = 0; kc < 3; kc++){
            LDSM4(ah[kc], aoffH + 32 * kc);
            LDSM4(al[kc], aoffL + 32 * kc);
        }
        __syncwarp();

        #pragma unroll
        for (int npp = 0; npp < 4; npp++){
            float dIF0[4] = {0.f,0.f,0.f,0.f};
            float dIF1[4] = {0.f,0.f,0.f,0.f};
            float dGO0[4] = {0.f,0.f,0.f,0.f};
            float dGO1[4] = {0.f,0.f,0.f,0.f};
            #pragma unroll
            for (int kc = 0; kc < 3; kc++){
                uint32_t bIFh[4], bIFl[4], bGOh[4], bGOl[4];
                LDSM4(bIFh, boffH[npp]     + 32 * kc);
                LDSM4(bIFl, boffH[npp]     + 16384 + 32 * kc);
                LDSM4(bGOh, boffH[npp + 4] + 32 * kc);
                LDSM4(bGOl, boffH[npp + 4] + 16384 + 32 * kc);
                // regs {0,1} = n-tile 2np, {2,3} = n-tile 2np+1
                MMA_BF16(dIF0, ah[kc], bIFh[0], bIFh[1]);
                MMA_BF16(dIF0, ah[kc], bIFl[0], bIFl[1]);
                MMA_BF16(dIF0, al[kc], bIFh[0], bIFh[1]);
                MMA_BF16(dIF1, ah[kc], bIFh[2], bIFh[3]);
                MMA_BF16(dIF1, ah[kc], bIFl[2], bIFl[3]);
                MMA_BF16(dIF1, al[kc], bIFh[2], bIFh[3]);
                MMA_BF16(dGO0, ah[kc], bGOh[0], bGOh[1]);
                MMA_BF16(dGO0, ah[kc], bGOl[0], bGOl[1]);
                MMA_BF16(dGO0, al[kc], bGOh[0], bGOh[1]);
                MMA_BF16(dGO1, ah[kc], bGOh[2], bGOh[3]);
                MMA_BF16(dGO1, ah[kc], bGOl[2], bGOl[3]);
                MMA_BF16(dGO1, al[kc], bGOh[2], bGOh[3]);
            }
            const int vA = 8 * npp + q;
            const int vB = vA + 4;
            #pragma unroll
            for (int e = 0; e < 4; e++){
                // e: 0=(vA,row0) 1=(vA,row1) 2=(vB,row0) 3=(vB,row1)
                const float* dif = (e < 2) ? dIF0 : dIF1;
                const float* dgo = (e < 2) ? dGO0 : dGO1;
                int half = (e & 1) * 2;
                float zi = dif[half], zf = dif[half + 1];
                float zg = dgo[half], zo = dgo[half + 1];
                float ii = sigt(zi), ff = sigt(zf);
                float gg = tanha(zg), oo = sigt(zo);
                float cv = ff * cst[npp * 4 + e] + ii * gg;
                cst[npp * 4 + e] = cv;
                float h = oo * tanha(cv);
                int v  = (e < 2) ? vA : vB;
                int rw = (e & 1) ? row1 : row0;
                uint32_t off = SWZ((uint32_t)(rw * 128 + v * 2));
                __nv_bfloat16 hh = __float2bfloat16(h);
                float hl = h - __bfloat162float(hh);
                *(__nv_bfloat16*)(smc + OFF_AH + off) = hh;
                *(__nv_bfloat16*)(smc + OFF_AL + off) = __float2bfloat16(hl);
            }
        }
        __syncwarp();
    }

    // --- zx epilogue: h = hi + lo (err ~2^-18). Rows of this warp only
    // are read by tids 32w..32w+31 (row = tid>>1), so __syncwarp suffices.
    __syncwarp();
    {
        const int row = tid >> 1;          // 0..127 (within this warp's 16)
        const int cg  = tid & 1;           // col half: 48 cols
        const float* wos = (float*)(smc + OFF_WO);
        const float* bos = (float*)(smc + OFF_BO);
        float4 acc[12];
        #pragma unroll
        for (int j = 0; j < 12; j++)
            acc[j] = *(const float4*)(bos + cg * 48 + j * 4);
        #pragma unroll 4
        for (int k = 0; k < 32; k++){
            uint32_t off = SWZ((uint32_t)(row * 128 + k * 2));
            float hk = __bfloat162float(*(__nv_bfloat16*)(smc + OFF_AH + off))
                     + __bfloat162float(*(__nv_bfloat16*)(smc + OFF_AL + off));
            const float4* wp = (const float4*)(wos + k * 96 + cg * 48);
            #pragma unroll
            for (int j = 0; j < 12; j++){
                float4 w = wp[j];
                acc[j].x = fmaf(hk, w.x, acc[j].x);
                acc[j].y = fmaf(hk, w.y, acc[j].y);
                acc[j].z = fmaf(hk, w.z, acc[j].z);
                acc[j].w = fmaf(hk, w.w, acc[j].w);
            }
        }
        float* zp = g_zx + ((size_t)blockIdx.x * 128 + row) * 96 + cg * 48;
        #pragma unroll
        for (int j = 0; j < 12; j++) *(float4*)(zp + j * 4) = acc[j];
    }
}

// =====================================================================
// Outer LSTM + dense head (R6 version, 93us): one warp per batch row,
// register weights, static depth-2 prefetch, split chains.
// =====================================================================
__device__ __forceinline__ void outer_step(
    float& h, float& c, u64 zA, u64 zB,
    const u64* w_if, const u64* w_go)
{
    u64 a0 = zA, a1 = 0ULL, b0 = zB, b1 = 0ULL;
    #pragma unroll
    for (int j = 0; j < 12; j++){
        float h0 = __shfl_sync(0xffffffffu, h, j);
        float h1 = __shfl_sync(0xffffffffu, h, j + 12);
        u64 H0 = pk2(h0, h0), H1 = pk2(h1, h1);
        a0 = ffma2(H0, w_if[j],      a0);
        b0 = ffma2(H0, w_go[j],      b0);
        a1 = ffma2(H1, w_if[j + 12], a1);
        b1 = ffma2(H1, w_go[j + 12], b1);
    }
    u64 zAf = add2(a0, a1);
    u64 zBf = add2(b0, b1);
    float zi, zf, zg, zo;
    up2(zAf, zi, zf);
    up2(zBf, zg, zo);
    float fi = sigt(zi), ff = sigt(zf), gg = tanha(zg), oo = sigt(zo);
    c = fmaf(ff, c, fi * gg);
    h = oo * tanha(c);
}

__global__ void __launch_bounds__(32) outer_kernel(
    const int*   __restrict__ lengths,
    const float* __restrict__ Uo,
    const float* __restrict__ Wd,
    const float* __restrict__ bd,
    float*       __restrict__ out)
{
    const int l  = threadIdx.x;
    const int la = (l < 24) ? l : 0;
    const int b  = blockIdx.x;

    u64 w_if[24], w_go[24];
    #pragma unroll
    for (int k = 0; k < 24; k++){
        const float* row = Uo + k * 96;
        w_if[k] = pk2(__ldg(row + la),      __ldg(row + 24 + la));
        w_go[k] = pk2(__ldg(row + 48 + la), __ldg(row + 72 + la));
    }

    const int len = lengths[b];
    const float* zr = g_zx + (size_t)b * Tn * 96;

    u64 A0, B0, A1, B1;
    A0 = pk2(zr[la], zr[24 + la]);
    B0 = pk2(zr[48 + la], zr[72 + la]);
    {
        const float* z1 = zr + ((len > 1) ? 96 : 0);
        A1 = pk2(z1[la], z1[24 + la]);
        B1 = pk2(z1[48 + la], z1[72 + la]);
    }

    float h = 0.f, c = 0.f;
    int t = 0;
    while (t < len){
        {
            u64 zA = A0, zB = B0;
            int tp = (t + 2 < len) ? t + 2 : len - 1;
            const float* zq = zr + (size_t)tp * 96;
            A0 = pk2(zq[la], zq[24 + la]);
            B0 = pk2(zq[48 + la], zq[72 + la]);
            outer_step(h, c, zA, zB, w_if, w_go);
        }
        t++;
        if (t >= len) break;
        {
            u64 zA = A1, zB = B1;
            int tp = (t + 2 < len) ? t + 2 : len - 1;
            const float* zq = zr + (size_t)tp * 96;
            A1 = pk2(zq[la], zq[24 + la]);
            B1 = pk2(zq[48 + la], zq[72 + la]);
            outer_step(h, c, zA, zB, w_if, w_go);
        }
        t++;
    }

    float p = (l < 24) ? h * __ldg(Wd + la) : 0.f;
    #pragma unroll
    for (int off = 16; off; off >>= 1) p += __shfl_xor_sync(0xffffffffu, p, off);
    if (l == 0) out[b] = fmaf(0.5f, tanha(0.5f * (p + bd[0])), 0.5f);
}

extern "C" void kernel_launch(void* const* d_in, const int* in_sizes, int n_in,
                              void* d_out, int out_size)
{
    const float* x       = (const float*)d_in[0];
    const int*   lengths = (const int*)  d_in[1];
    const float* Wi      = (const float*)d_in[2];
    const float* Ui      = (const float*)d_in[3];
    const float* bi      = (const float*)d_in[4];
    const float* Wo      = (const float*)d_in[5];
    const float* Uo      = (const float*)d_in[6];
    const float* bo      = (const float*)d_in[7];
    const float* Wd      = (const float*)d_in[8];
    const float* bd      = (const float*)d_in[9];
    float* out = (float*)d_out;

    cudaFuncSetAttribute(inner_mma,
                         cudaFuncAttributeMaxDynamicSharedMemorySize, SMEM_SZ);

    inner_mma<<<512, 256, SMEM_SZ>>>(x, Wi, Ui, bi, Wo, bo);
    outer_kernel<<<256, 32>>>(lengths, Uo, Wd, bd, out);
}